// round 4
// baseline (speedup 1.0000x reference)
#include <cuda_runtime.h>
#include <cuda_bf16.h>
#include <float.h>

#define BZ    64
#define SEQ   2048
#define DIM   2048
#define NE    16
#define RK    4
#define DCH   8                 // DIM chunks (blocks in y)
#define LANES (DIM / DCH / 4)   // 64 float4 lanes per block
#define TPB   256
#define RG    (TPB / LANES)     // 4 row-groups per block
#define RPG   (SEQ / RG)        // 512 rows per row-group
#define NWARP (TPB / 32)        // 8 warps

// Partial logits per (dc, b, e). Summed in fixed order by the finalizer.
__device__ float g_p1[DCH * BZ * NE];
__device__ float g_p2[DCH * BZ * NE];
__device__ int   g_count;       // zero-init; last block resets to 0 each run

__global__ __launch_bounds__(TPB) void fused_selector(
    const float* __restrict__ x,
    const int*   __restrict__ idx,
    const float* __restrict__ W_b,
    const float* __restrict__ embed,
    const float* __restrict__ W_c,
    float*       __restrict__ out,
    int out_size)
{
    const int b    = blockIdx.x;
    const int dc   = blockIdx.y;
    const int t    = threadIdx.x;         // 0..255
    const int l    = t & (LANES - 1);     // float4 lane within slice (0..63)
    const int g    = t / LANES;           // row-group 0..3
    const int lane = t & 31;
    const int warp = t >> 5;              // 8 warps

    const int dbase4 = dc * LANES;        // float4 offset of slice within a row

    // ---- main streaming loop: sum x[b, g*RPG..(g+1)*RPG, slice] ----
    const float4* __restrict__ xp =
        reinterpret_cast<const float4*>(x)
        + ((size_t)b * SEQ + (size_t)g * RPG) * (DIM / 4) + dbase4 + l;

    float4 a0 = make_float4(0.f, 0.f, 0.f, 0.f);
    float4 a1 = a0, a2 = a0, a3 = a0;

    #pragma unroll 2
    for (int s = 0; s < RPG; s += 8) {
        // 8 independent streaming loads issued front-batched (MLP_p1 = 8)
        float4 v0 = __ldcs(&xp[(size_t)(s + 0) * (DIM / 4)]);
        float4 v1 = __ldcs(&xp[(size_t)(s + 1) * (DIM / 4)]);
        float4 v2 = __ldcs(&xp[(size_t)(s + 2) * (DIM / 4)]);
        float4 v3 = __ldcs(&xp[(size_t)(s + 3) * (DIM / 4)]);
        float4 v4 = __ldcs(&xp[(size_t)(s + 4) * (DIM / 4)]);
        float4 v5 = __ldcs(&xp[(size_t)(s + 5) * (DIM / 4)]);
        float4 v6 = __ldcs(&xp[(size_t)(s + 6) * (DIM / 4)]);
        float4 v7 = __ldcs(&xp[(size_t)(s + 7) * (DIM / 4)]);
        a0.x += v0.x; a0.y += v0.y; a0.z += v0.z; a0.w += v0.w;
        a1.x += v1.x; a1.y += v1.y; a1.z += v1.z; a1.w += v1.w;
        a2.x += v2.x; a2.y += v2.y; a2.z += v2.z; a2.w += v2.w;
        a3.x += v3.x; a3.y += v3.y; a3.z += v3.z; a3.w += v3.w;
        a0.x += v4.x; a0.y += v4.y; a0.z += v4.z; a0.w += v4.w;
        a1.x += v5.x; a1.y += v5.y; a1.z += v5.z; a1.w += v5.w;
        a2.x += v6.x; a2.y += v6.y; a2.z += v6.z; a2.w += v6.w;
        a3.x += v7.x; a3.y += v7.y; a3.z += v7.z; a3.w += v7.w;
    }
    float4 r;
    r.x = (a0.x + a1.x) + (a2.x + a3.x);
    r.y = (a0.y + a1.y) + (a2.y + a3.y);
    r.z = (a0.z + a1.z) + (a2.z + a3.z);
    r.w = (a0.w + a1.w) + (a2.w + a3.w);

    // ---- epilogue: W_b dot on this slice (L2/L1 resident) ----
    const float4* __restrict__ wb4 = reinterpret_cast<const float4*>(W_b);
    float p1[NE];
    #pragma unroll
    for (int e = 0; e < NE; e++) {
        float4 w = wb4[(size_t)e * (DIM / 4) + dbase4 + l];
        p1[e] = (r.x * w.x + r.y * w.y) + (r.z * w.z + r.w * w.w);
    }

    // ---- embed-mean dot W_c on this slice (row-group 0 only) ----
    float p2[NE];
    #pragma unroll
    for (int e = 0; e < NE; e++) p2[e] = 0.f;
    if (g == 0) {
        const int i0 = idx[b * RK + 0];
        const int i1 = idx[b * RK + 1];
        const int i2 = idx[b * RK + 2];
        const int i3 = idx[b * RK + 3];
        const float4* __restrict__ em4 = reinterpret_cast<const float4*>(embed);
        const float4* __restrict__ wc4 = reinterpret_cast<const float4*>(W_c);
        float4 e0 = em4[(size_t)i0 * (DIM / 4) + dbase4 + l];
        float4 e1 = em4[(size_t)i1 * (DIM / 4) + dbase4 + l];
        float4 e2 = em4[(size_t)i2 * (DIM / 4) + dbase4 + l];
        float4 e3 = em4[(size_t)i3 * (DIM / 4) + dbase4 + l];
        float4 h;
        h.x = 0.25f * ((e0.x + e1.x) + (e2.x + e3.x));
        h.y = 0.25f * ((e0.y + e1.y) + (e2.y + e3.y));
        h.z = 0.25f * ((e0.z + e1.z) + (e2.z + e3.z));
        h.w = 0.25f * ((e0.w + e1.w) + (e2.w + e3.w));
        #pragma unroll
        for (int e = 0; e < NE; e++) {
            float4 w = wc4[(size_t)e * (DIM / 4) + dbase4 + l];
            p2[e] = (h.x * w.x + h.y * w.y) + (h.z * w.z + h.w * w.w);
        }
    }

    // ---- warp reduce (each warp covers 32 distinct d-lanes) ----
    #pragma unroll
    for (int e = 0; e < NE; e++) {
        #pragma unroll
        for (int off = 16; off > 0; off >>= 1) {
            p1[e] += __shfl_down_sync(0xFFFFFFFFu, p1[e], off);
            if (warp < 2) p2[e] += __shfl_down_sync(0xFFFFFFFFu, p2[e], off);
        }
    }

    __shared__ float s1[NWARP][NE];
    __shared__ float s2[2][NE];
    __shared__ int   s_amLast;
    if (lane == 0) {
        #pragma unroll
        for (int e = 0; e < NE; e++) s1[warp][e] = p1[e];
        if (warp < 2) {
            #pragma unroll
            for (int e = 0; e < NE; e++) s2[warp][e] = p2[e];
        }
    }
    __syncthreads();

    if (t < NE) {
        float v1 = 0.f;
        #pragma unroll
        for (int w = 0; w < NWARP; w++) v1 += s1[w][t];
        g_p1[((size_t)dc * BZ + b) * NE + t] = v1;
        g_p2[((size_t)dc * BZ + b) * NE + t] = s2[0][t] + s2[1][t];
        __threadfence();
    }
    __syncthreads();

    if (t == 0) {
        int ticket = atomicAdd(&g_count, 1);
        s_amLast = (ticket == (int)(gridDim.x * gridDim.y) - 1);
    }
    __syncthreads();
    if (!s_amLast) return;
    __threadfence();  // acquire: see all blocks' g_p writes

    // ---- finalize: one thread per batch row ----
    if (t < BZ) {
        const int bb = t;
        float l1[NE], l2[NE];
        #pragma unroll
        for (int e = 0; e < NE; e++) {
            float v1 = 0.f, v2 = 0.f;
            #pragma unroll
            for (int d = 0; d < DCH; d++) {
                v1 += g_p1[((size_t)d * BZ + bb) * NE + e];
                v2 += g_p2[((size_t)d * BZ + bb) * NE + e];
            }
            l1[e] = v1 * (1.0f / (float)SEQ);
            l2[e] = v2;
        }

        float m1 = -FLT_MAX, m2 = -FLT_MAX;
        #pragma unroll
        for (int e = 0; e < NE; e++) { m1 = fmaxf(m1, l1[e]); m2 = fmaxf(m2, l2[e]); }
        float z1 = 0.f, z2 = 0.f;
        float sm1[NE], sm2[NE];
        #pragma unroll
        for (int e = 0; e < NE; e++) {
            sm1[e] = __expf(l1[e] - m1); z1 += sm1[e];
            sm2[e] = __expf(l2[e] - m2); z2 += sm2[e];
        }
        const float iz1 = 1.f / z1, iz2 = 1.f / z2;
        float logits[NE], score[NE];
        float mC = -FLT_MAX;
        #pragma unroll
        for (int e = 0; e < NE; e++) {
            logits[e] = sm1[e] * iz1 + sm2[e] * iz2;  // IFS_WEIGHT = 1.0
            mC = fmaxf(mC, logits[e]);
        }

        // top-4: strict > keeps lowest index on ties; descending order
        int  topk[RK];
        bool taken[NE];
        #pragma unroll
        for (int e = 0; e < NE; e++) taken[e] = false;
        #pragma unroll
        for (int r2 = 0; r2 < RK; r2++) {
            float best = -FLT_MAX;
            int   bi   = 0;
            #pragma unroll
            for (int e = 0; e < NE; e++)
                if (!taken[e] && logits[e] > best) { best = logits[e]; bi = e; }
            taken[bi] = true;
            topk[r2] = bi;
        }

        float zC = 0.f;
        #pragma unroll
        for (int e = 0; e < NE; e++) { score[e] = __expf(logits[e] - mC); zC += score[e]; }
        const float izC = 1.f / zC;
        float denom = 0.f;
        #pragma unroll
        for (int e = 0; e < NE; e++) {
            score[e] *= izC;
            if (taken[e]) denom += score[e];
        }
        denom = fmaxf(denom, FLT_EPSILON);
        const float inv_d = 1.f / denom;

        if (out_size >= BZ * NE) {
            #pragma unroll
            for (int e = 0; e < NE; e++)
                out[bb * NE + e] = taken[e] ? score[e] * inv_d : 0.f;
        }
        if (out_size >= BZ * NE + BZ * RK) {
            #pragma unroll
            for (int r2 = 0; r2 < RK; r2++)
                out[BZ * NE + bb * RK + r2] = (float)topk[r2];
        }
    }
    __syncthreads();
    if (t == 0) g_count = 0;   // reset for next graph replay
}

extern "C" void kernel_launch(void* const* d_in, const int* in_sizes, int n_in,
                              void* d_out, int out_size) {
    const float* x     = (const float*)d_in[0];
    const int*   idx   = (const int*)  d_in[1];
    const float* W_b   = (const float*)d_in[2];
    const float* embed = (const float*)d_in[3];
    const float* W_c   = (const float*)d_in[4];
    float* out = (float*)d_out;

    dim3 grid(BZ, DCH);
    fused_selector<<<grid, TPB>>>(x, idx, W_b, embed, W_c, out, out_size);
}